// round 9
// baseline (speedup 1.0000x reference)
#include <cuda_runtime.h>
#include <cstdint>

#define NPTS   16384
#define NPOINT 1024
#define NBATCH 4
#define CSIZE  4                  // CTAs cooperating per batch
#define NTHR   512
#define NWARP  16
#define PPT    8                  // register-resident points per thread
#define NROUND 1024               // sync rounds

// 32B slot per (batch, round, rank): [0]=key|tag, [1]=x|y, [2]=z, [3]=pad.
// Write-once per round per run; replay-safe (deterministic identical bits,
// word-atomic stores, tag 0 never matches).
__device__ unsigned long long g_slot[NBATCH][NROUND][CSIZE][4];

// key = bits(dist)<<32 | (~idx & 0x3FFF)<<11 | tag   (tag = r+1, 1..1024)
__device__ __forceinline__ unsigned long long pack_key(float v, int idx,
                                                       unsigned tag) {
    return ((unsigned long long)__float_as_uint(v) << 32)
         | (unsigned)((((~idx) & 0x3FFF) << 11) | tag);
}
__device__ __forceinline__ int key_idx(unsigned long long k) {
    return (~((unsigned)(k >> 11))) & 0x3FFF;
}

// ---------------------------------------------------------------------------
// Cross-CTA argmax carrying winner coordinates. Resolves round r:
//   s_cent[r] = winning global index, s_c[0..2] = its coords.
// ---------------------------------------------------------------------------
__device__ __forceinline__ void sync_argmax(
        float mv, int mi, float wx, float wy, float wz,
        int b, int r, uint32_t rank,
        unsigned long long* s_wkey, float* s_wc,   // [NWARP], [3*NWARP]
        int* s_cent, float* s_c) {
    const int tid  = threadIdx.x;
    const int warp = tid >> 5;
    const int lane = tid & 31;
    const unsigned tag = (unsigned)(r + 1);

    unsigned long long key = pack_key(mv, mi, tag);
    #pragma unroll
    for (int off = 16; off > 0; off >>= 1) {
        unsigned long long ok = __shfl_down_sync(0xffffffffu, key, off);
        float ox = __shfl_down_sync(0xffffffffu, wx, off);
        float oy = __shfl_down_sync(0xffffffffu, wy, off);
        float oz = __shfl_down_sync(0xffffffffu, wz, off);
        if (ok > key) { key = ok; wx = ox; wy = oy; wz = oz; }
    }
    if (lane == 0) {
        s_wkey[warp] = key;
        s_wc[warp * 3 + 0] = wx;
        s_wc[warp * 3 + 1] = wy;
        s_wc[warp * 3 + 2] = wz;
    }
    __syncthreads();

    if (warp == 0) {
        const int l = lane & (NWARP - 1);
        unsigned long long k2 = s_wkey[l];
        float x2 = s_wc[l * 3 + 0], y2 = s_wc[l * 3 + 1], z2 = s_wc[l * 3 + 2];
        if (lane >= NWARP) k2 = 0ULL;
        #pragma unroll
        for (int off = 8; off > 0; off >>= 1) {
            unsigned long long ok = __shfl_down_sync(0xffffffffu, k2, off);
            float ox = __shfl_down_sync(0xffffffffu, x2, off);
            float oy = __shfl_down_sync(0xffffffffu, y2, off);
            float oz = __shfl_down_sync(0xffffffffu, z2, off);
            if (ok > k2) { k2 = ok; x2 = ox; y2 = oy; z2 = oz; }
        }
        if (lane == 0) {
            unsigned long long* p = &g_slot[b][r][rank][0];
            const unsigned long long xy =
                (unsigned long long)__float_as_uint(x2)
              | ((unsigned long long)__float_as_uint(y2) << 32);
            const unsigned long long zz = (unsigned long long)__float_as_uint(z2);
            asm volatile("st.relaxed.gpu.global.u64 [%0], %1;"
                         :: "l"(p + 1), "l"(xy) : "memory");
            asm volatile("st.relaxed.gpu.global.u64 [%0], %1;"
                         :: "l"(p + 2), "l"(zz) : "memory");
            asm volatile("st.release.gpu.global.u64 [%0], %1;"
                         :: "l"(p), "l"(k2) : "memory");
        }

        // poll the 4 slots (one per lane), then combine
        unsigned long long kj = 0ULL, xyj = 0ULL, zj = 0ULL;
        if (lane < CSIZE) {
            const unsigned long long* p = &g_slot[b][r][lane][0];
            do {
                asm volatile("ld.acquire.gpu.global.u64 %0, [%1];"
                             : "=l"(kj) : "l"(p) : "memory");
            } while ((unsigned)(kj & 0x7FFu) != tag);
            asm volatile("ld.relaxed.gpu.global.u64 %0, [%1];"
                         : "=l"(xyj) : "l"(p + 1) : "memory");
            asm volatile("ld.relaxed.gpu.global.u64 %0, [%1];"
                         : "=l"(zj) : "l"(p + 2) : "memory");
        }
        #pragma unroll
        for (int off = 2; off > 0; off >>= 1) {
            unsigned long long ok = __shfl_down_sync(0xffffffffu, kj,  off);
            unsigned long long oxy = __shfl_down_sync(0xffffffffu, xyj, off);
            unsigned long long oz = __shfl_down_sync(0xffffffffu, zj,  off);
            if (ok > kj) { kj = ok; xyj = oxy; zj = oz; }
        }
        if (lane == 0) {
            s_cent[r] = key_idx(kj);
            s_c[0] = __uint_as_float((unsigned)xyj);
            s_c[1] = __uint_as_float((unsigned)(xyj >> 32));
            s_c[2] = __uint_as_float((unsigned)zj);
        }
    }
    __syncthreads();
}

// ---------------------------------------------------------------------------
// Fused FPS + ball query. 4 cooperating CTAs per batch, plain launch.
// FP semantics identical to validated kernels; float32 output.
// ---------------------------------------------------------------------------
__global__ void __launch_bounds__(NTHR, 1)
fps_mc_kernel(const float* __restrict__ xyz, float* __restrict__ out) {
    __shared__ unsigned long long s_wkey[NWARP];
    __shared__ float s_wc[3 * NWARP];
    __shared__ int   s_cent[NPOINT];
    __shared__ float s_c[3];

    const int tid  = threadIdx.x;
    const int warp = tid >> 5;
    const int lane = tid & 31;
    const int b    = blockIdx.x >> 2;
    const uint32_t rank = (uint32_t)(blockIdx.x & 3);

    const float* __restrict__ base = xyz + (size_t)b * 3 * NPTS;
    const float4* __restrict__ X4 = (const float4*)base;
    const float4* __restrict__ Y4 = X4 + NPTS / 4;
    const float4* __restrict__ Z4 = Y4 + NPTS / 4;

    // ---- load this CTA's 8 points/thread into registers ----
    float px[PPT], py[PPT], pz[PPT], dist[PPT];
    #pragma unroll
    for (int c = 0; c < 2; c++) {
        const int f4 = (int)rank * 1024 + c * NTHR + tid;
        const float4 X = __ldg(&X4[f4]);
        const float4 Y = __ldg(&Y4[f4]);
        const float4 Z = __ldg(&Z4[f4]);
        px[c*4+0] = X.x; px[c*4+1] = X.y; px[c*4+2] = X.z; px[c*4+3] = X.w;
        py[c*4+0] = Y.x; py[c*4+1] = Y.y; py[c*4+2] = Y.z; py[c*4+3] = Y.w;
        pz[c*4+0] = Z.x; pz[c*4+1] = Z.y; pz[c*4+2] = Z.z; pz[c*4+3] = Z.w;
    }
    const int pb = ((int)rank * 1024 + tid) * 4;  // chunk0 base; chunk1 = +2048
    #pragma unroll
    for (int i = 0; i < PPT; i++) dist[i] = 1e10f;

    // ---- round 0: argmax over x (first occurrence), coords carried ----
    {
        float mv = -3.402823466e38f; int mi = 0;
        float wx = 0.f, wy = 0.f, wz = 0.f;
        #pragma unroll
        for (int i = 0; i < PPT; i++) {
            const int p = ((i < 4) ? pb : (pb + 2048)) + (i & 3);
            if (px[i] > mv) {
                mv = px[i]; mi = p;
                wx = px[i]; wy = py[i]; wz = pz[i];
            }
        }
        sync_argmax(mv, mi, wx, wy, wz, b, 0, rank,
                    s_wkey, s_wc, s_cent, s_c);
    }

    // ---- FPS main loop: round r resolves s_cent[r]; loop uses coords ----
    for (int k = 0; k < NPOINT - 1; k++) {
        const float cx = s_c[0];
        const float cy = s_c[1];
        const float cz = s_c[2];

        float mv = -1.0f; int mi = 0;
        float wx = 0.f, wy = 0.f, wz = 0.f;
        #pragma unroll
        for (int i = 0; i < PPT; i++) {
            const float dx = __fsub_rn(px[i], cx);
            const float dy = __fsub_rn(py[i], cy);
            const float dz = __fsub_rn(pz[i], cz);
            const float d  = __fmaf_rn(dz, dz,
                             __fmaf_rn(dy, dy, __fmul_rn(dx, dx)));
            const float dd = fminf(dist[i], d);
            dist[i] = dd;
            if (dd > mv) {
                mv = dd;
                mi = ((i < 4) ? pb : (pb + 2048)) + (i & 3);
                wx = px[i]; wy = py[i]; wz = pz[i];
            }
        }
        sync_argmax(mv, mi, wx, wy, wz, b, k + 1, rank,
                    s_wkey, s_wc, s_cent, s_c);
    }
    // s_cent[0..1023] complete in every CTA

    // ---- ball query: this CTA handles 256 of the 1024 centroids ----
    const int gw = (int)rank * NWARP + warp;            // 0..63 per batch
    for (int t = 0; t < NPOINT / (CSIZE * NWARP); t++) {
        const int s = t * (CSIZE * NWARP) + gw;
        const int c = s_cent[s];
        const float xs = __ldg(&base[c]);
        const float ys = __ldg(&base[NPTS + c]);
        const float zs = __ldg(&base[2 * NPTS + c]);
        const float snorm = __fmaf_rn(zs, zs,
                            __fmaf_rn(ys, ys, __fmul_rn(xs, xs)));

        int winner = NPTS;
        for (int j0 = 0; j0 < NPTS; j0 += 32) {
            const int j = j0 + lane;
            const float xj = __ldg(&base[j]);
            const float yj = __ldg(&base[NPTS + j]);
            const float zj = __ldg(&base[2 * NPTS + j]);
            const float dot   = __fmaf_rn(zs, zj,
                                __fmaf_rn(ys, yj, __fmul_rn(xs, xj)));
            const float dnorm = __fmaf_rn(zj, zj,
                                __fmaf_rn(yj, yj, __fmul_rn(xj, xj)));
            const float d = __fadd_rn(__fmaf_rn(-2.0f, dot, snorm), dnorm);
            const unsigned m = __ballot_sync(0xffffffffu, !(d > 0.25f));
            if (m) { winner = j0 + __ffs(m) - 1; break; }
        }
        if (lane == 0) out[b * NPOINT + s] = (float)winner;
    }
}

// ---------------------------------------------------------------------------
extern "C" void kernel_launch(void* const* d_in, const int* in_sizes, int n_in,
                              void* d_out, int out_size) {
    int xi = 0;
    for (int i = 0; i < n_in; i++) {
        if (in_sizes[i] == NBATCH * 3 * NPTS) { xi = i; break; }
    }
    const float* xyz = (const float*)d_in[xi];
    float* out = (float*)d_out;

    fps_mc_kernel<<<NBATCH * CSIZE, NTHR>>>(xyz, out);
}

// round 10
// speedup vs baseline: 1.0348x; 1.0348x over previous
#include <cuda_runtime.h>
#include <cstdint>

#define NPTS   16384
#define NPOINT 1024
#define NBATCH 4
#define NTHR   1024
#define NWARP  32
#define CHUNKS 4                  // float4 chunks per thread
#define PPT    16                 // points per thread

// key = bits(v)<<32 | ~idx  — v >= 0 so IEEE order == unsigned order;
// ~idx resolves ties to the SMALLEST index (first occurrence) under max.
__device__ __forceinline__ unsigned long long pack_key(float v, int idx) {
    return ((unsigned long long)__float_as_uint(v) << 32)
         | (unsigned)(~idx);
}

// ---------------------------------------------------------------------------
// One-barrier block argmax: warp shfl reduce -> STS -> BAR -> every warp
// redundantly reduces the 32 warp keys. Returns winning index to ALL threads.
// s_wkey is double-buffered by the caller (parity) to avoid WAR races.
// ---------------------------------------------------------------------------
__device__ __forceinline__ int block_argmax(float mv, int mi,
                                            unsigned long long* s_wkey) {
    const int warp = threadIdx.x >> 5;
    const int lane = threadIdx.x & 31;

    unsigned long long key = pack_key(mv, mi);
    #pragma unroll
    for (int off = 16; off > 0; off >>= 1) {
        const unsigned long long o = __shfl_down_sync(0xffffffffu, key, off);
        if (o > key) key = o;
    }
    if (lane == 0) s_wkey[warp] = key;
    __syncthreads();

    // redundant top-level reduce in every warp (no second barrier)
    unsigned long long k = s_wkey[lane];
    #pragma unroll
    for (int off = 16; off > 0; off >>= 1) {
        const unsigned long long o = __shfl_down_sync(0xffffffffu, k, off);
        if (o > k) k = o;
    }
    k = __shfl_sync(0xffffffffu, k, 0);     // broadcast within warp
    return (int)(~(unsigned)k);             // low 32 = ~idx
}

// ---------------------------------------------------------------------------
// Fused FPS + ball query. One CTA (1024 thr) per batch. xyz layout [B,3,N].
// FP semantics identical to the validated round-5 kernel:
//   d = fma(dz,dz, fma(dy,dy, dx*dx)), dist = fminf(dist,d),
//   first-occurrence argmax, PRE-update farthest recorded, float32 output.
// ---------------------------------------------------------------------------
__global__ void __launch_bounds__(NTHR, 1)
fps_kernel(const float* __restrict__ xyz, float* __restrict__ out) {
    __shared__ unsigned long long s_wkey[2][NWARP];   // parity double-buffer
    __shared__ int s_cent[NPOINT];

    const int tid  = threadIdx.x;
    const int warp = tid >> 5;
    const int lane = tid & 31;
    const int b    = blockIdx.x;

    const float* __restrict__ base = xyz + (size_t)b * 3 * NPTS;
    const float4* __restrict__ X4 = (const float4*)base;
    const float4* __restrict__ Y4 = X4 + NPTS / 4;
    const float4* __restrict__ Z4 = Y4 + NPTS / 4;

    // ---- initial farthest = argmax over x (first occurrence) ----
    int far;
    {
        float mv = -3.402823466e38f; int mi = 0;
        #pragma unroll
        for (int c = 0; c < CHUNKS; c++) {
            const float4 X = __ldg(&X4[c * NTHR + tid]);
            const int p = (c * NTHR + tid) * 4;
            if (X.x > mv) { mv = X.x; mi = p;     }
            if (X.y > mv) { mv = X.y; mi = p + 1; }
            if (X.z > mv) { mv = X.z; mi = p + 2; }
            if (X.w > mv) { mv = X.w; mi = p + 3; }
        }
        far = block_argmax(mv, mi, s_wkey[0]);
    }

    float dist[PPT];
    #pragma unroll
    for (int i = 0; i < PPT; i++) dist[i] = 1e10f;

    // ---- FPS main loop ----
    for (int k = 0; k < NPOINT; k++) {
        if (tid == 0) s_cent[k] = far;

        // uniform-address L1-hit broadcast loads
        const float cx = __ldg(&base[far]);
        const float cy = __ldg(&base[NPTS + far]);
        const float cz = __ldg(&base[2 * NPTS + far]);

        float mv = -1.0f; int mi = 0;
        #pragma unroll
        for (int c = 0; c < CHUNKS; c++) {
            const float4 X = __ldg(&X4[c * NTHR + tid]);
            const float4 Y = __ldg(&Y4[c * NTHR + tid]);
            const float4 Z = __ldg(&Z4[c * NTHR + tid]);
            const int p = (c * NTHR + tid) * 4;
            const float xs[4] = {X.x, X.y, X.z, X.w};
            const float ys[4] = {Y.x, Y.y, Y.z, Y.w};
            const float zs[4] = {Z.x, Z.y, Z.z, Z.w};
            #pragma unroll
            for (int e = 0; e < 4; e++) {
                const float dx = __fsub_rn(xs[e], cx);
                const float dy = __fsub_rn(ys[e], cy);
                const float dz = __fsub_rn(zs[e], cz);
                const float d  = __fmaf_rn(dz, dz,
                                 __fmaf_rn(dy, dy, __fmul_rn(dx, dx)));
                const float dd = fminf(dist[c * 4 + e], d);
                dist[c * 4 + e] = dd;
                if (dd > mv) { mv = dd; mi = p + e; }  // strict >: first occ.
            }
        }
        far = block_argmax(mv, mi, s_wkey[(k + 1) & 1]);
    }
    __syncthreads();   // s_cent complete

    // ---- ball query: 32 warps, 32 centroids each ----
    for (int s = warp; s < NPOINT; s += NWARP) {
        const int c = s_cent[s];
        const float xs = __ldg(&base[c]);
        const float ys = __ldg(&base[NPTS + c]);
        const float zs = __ldg(&base[2 * NPTS + c]);
        const float snorm = __fmaf_rn(zs, zs,
                            __fmaf_rn(ys, ys, __fmul_rn(xs, xs)));

        int winner = NPTS;
        for (int j0 = 0; j0 < NPTS; j0 += 32) {
            const int j = j0 + lane;
            const float xj = __ldg(&base[j]);
            const float yj = __ldg(&base[NPTS + j]);
            const float zj = __ldg(&base[2 * NPTS + j]);
            const float dot   = __fmaf_rn(zs, zj,
                                __fmaf_rn(ys, yj, __fmul_rn(xs, xj)));
            const float dnorm = __fmaf_rn(zj, zj,
                                __fmaf_rn(yj, yj, __fmul_rn(xj, xj)));
            const float d = __fadd_rn(__fmaf_rn(-2.0f, dot, snorm), dnorm);
            const unsigned m = __ballot_sync(0xffffffffu, !(d > 0.25f));
            if (m) { winner = j0 + __ffs(m) - 1; break; }
        }
        if (lane == 0) out[b * NPOINT + s] = (float)winner;
    }
}

// ---------------------------------------------------------------------------
extern "C" void kernel_launch(void* const* d_in, const int* in_sizes, int n_in,
                              void* d_out, int out_size) {
    int xi = 0;
    for (int i = 0; i < n_in; i++) {
        if (in_sizes[i] == NBATCH * 3 * NPTS) { xi = i; break; }
    }
    const float* xyz = (const float*)d_in[xi];
    float* out = (float*)d_out;

    fps_kernel<<<NBATCH, NTHR>>>(xyz, out);
}

// round 11
// speedup vs baseline: 1.4122x; 1.3647x over previous
#include <cuda_runtime.h>
#include <cstdint>

#define NPTS   16384
#define NPOINT 1024
#define NBATCH 4
#define NTHR   512
#define NWARP  16
#define CHUNKS 8                 // float4 chunks per thread (4 pts each)
#define PPT    32                // points per thread

// ---- packed f32x2 helpers (per-lane bit-identical to scalar rn ops) ----
#define PACK2(out, lo, hi) \
    asm("mov.b64 %0, {%1, %2};" : "=l"(out) : "f"(lo), "f"(hi))
#define UNPACK2(lo, hi, in) \
    asm("mov.b64 {%0, %1}, %2;" : "=f"(lo), "=f"(hi) : "l"(in))
#define ADD2(out, a, b) \
    asm("add.rn.f32x2 %0, %1, %2;" : "=l"(out) : "l"(a), "l"(b))
#define MUL2(out, a, b) \
    asm("mul.rn.f32x2 %0, %1, %2;" : "=l"(out) : "l"(a), "l"(b))
#define FMA2(out, a, b, c) \
    asm("fma.rn.f32x2 %0, %1, %2, %3;" : "=l"(out) : "l"(a), "l"(b), "l"(c))

// key = bits(v)<<32 | ~idx — v >= 0 so IEEE order == unsigned order;
// ~idx resolves ties to the SMALLEST index (first occurrence) under max.
__device__ __forceinline__ unsigned long long pack_key(float v, int idx) {
    return ((unsigned long long)__float_as_uint(v) << 32) | (unsigned)(~idx);
}

// ---------------------------------------------------------------------------
// One-barrier block argmax (16 warps): warp shfl reduce -> STS -> BAR ->
// every warp redundantly reduces the 16 warp keys (duplicated to 32 lanes).
// s_wkey double-buffered by caller (parity).
// ---------------------------------------------------------------------------
__device__ __forceinline__ int block_argmax(float mv, int mi,
                                            unsigned long long* s_wkey) {
    const int warp = threadIdx.x >> 5;
    const int lane = threadIdx.x & 31;

    unsigned long long key = pack_key(mv, mi);
    #pragma unroll
    for (int off = 16; off > 0; off >>= 1) {
        const unsigned long long o = __shfl_down_sync(0xffffffffu, key, off);
        if (o > key) key = o;
    }
    if (lane == 0) s_wkey[warp] = key;
    __syncthreads();

    unsigned long long k = s_wkey[lane & (NWARP - 1)];   // dup 0-15 -> 16-31
    #pragma unroll
    for (int off = 8; off > 0; off >>= 1) {
        const unsigned long long o = __shfl_down_sync(0xffffffffu, k, off);
        if (o > k) k = o;
    }
    k = __shfl_sync(0xffffffffu, k, 0);
    return (int)(~(unsigned)k);
}

// ---------------------------------------------------------------------------
// Fused FPS + ball query. One CTA (512 thr) per batch. xyz layout [B,3,N].
// x,y register-resident (packed f32x2), z re-read from L1 each step.
// Per-lane FP ops bit-identical to the validated round-5 kernel.
// ---------------------------------------------------------------------------
__global__ void __launch_bounds__(NTHR, 1)
fps_kernel(const float* __restrict__ xyz, float* __restrict__ out) {
    __shared__ unsigned long long s_wkey[2][NWARP];
    __shared__ int s_cent[NPOINT];

    const int tid  = threadIdx.x;
    const int warp = tid >> 5;
    const int lane = tid & 31;
    const int b    = blockIdx.x;

    const float* __restrict__ base = xyz + (size_t)b * 3 * NPTS;
    const float4* __restrict__ X4 = (const float4*)base;
    const float4* __restrict__ Y4 = X4 + NPTS / 4;
    const float4* __restrict__ Z4 = Y4 + NPTS / 4;

    // ---- load x,y into packed registers; do initial x-argmax on the fly ----
    unsigned long long ux[2 * CHUNKS], uy[2 * CHUNKS];
    float dist[PPT];
    float mv0 = -3.402823466e38f; int mi0 = 0;
    #pragma unroll
    for (int c = 0; c < CHUNKS; c++) {
        const float4 X = __ldg(&X4[c * NTHR + tid]);
        const float4 Y = __ldg(&Y4[c * NTHR + tid]);
        PACK2(ux[2*c],     X.x, X.y);
        PACK2(ux[2*c + 1], X.z, X.w);
        PACK2(uy[2*c],     Y.x, Y.y);
        PACK2(uy[2*c + 1], Y.z, Y.w);
        const int p = (c * NTHR + tid) * 4;
        if (X.x > mv0) { mv0 = X.x; mi0 = p;     }
        if (X.y > mv0) { mv0 = X.y; mi0 = p + 1; }
        if (X.z > mv0) { mv0 = X.z; mi0 = p + 2; }
        if (X.w > mv0) { mv0 = X.w; mi0 = p + 3; }
    }
    #pragma unroll
    for (int i = 0; i < PPT; i++) dist[i] = 1e10f;

    int far = block_argmax(mv0, mi0, s_wkey[0]);

    // ---- FPS main loop ----
    for (int k = 0; k < NPOINT; k++) {
        if (tid == 0) s_cent[k] = far;

        const float cx = __ldg(&base[far]);
        const float cy = __ldg(&base[NPTS + far]);
        const float cz = __ldg(&base[2 * NPTS + far]);
        const float ncx = -cx, ncy = -cy, ncz = -cz;
        unsigned long long ncxx, ncyy;
        PACK2(ncxx, ncx, ncx);
        PACK2(ncyy, ncy, ncy);

        float mv = -1.0f; int mi = 0;
        #pragma unroll
        for (int c = 0; c < CHUNKS; c++) {
            const float4 Z = __ldg(&Z4[c * NTHR + tid]);
            const int p = (c * NTHR + tid) * 4;
            const float zs[4] = {Z.x, Z.y, Z.z, Z.w};
            #pragma unroll
            for (int j = 0; j < 2; j++) {       // pair j covers pts e=2j,2j+1
                unsigned long long dx2, dy2, t2;
                ADD2(dx2, ux[2*c + j], ncxx);   // fadd(x,-cx) == fsub(x,cx)
                ADD2(dy2, uy[2*c + j], ncyy);
                MUL2(t2, dx2, dx2);
                FMA2(t2, dy2, dy2, t2);         // dy*dy + dx*dx
                float t0, t1;
                UNPACK2(t0, t1, t2);

                const float dz0 = __fadd_rn(zs[2*j],     ncz);
                const float dz1 = __fadd_rn(zs[2*j + 1], ncz);
                const float d0  = __fmaf_rn(dz0, dz0, t0);
                const float d1  = __fmaf_rn(dz1, dz1, t1);

                const int i0 = c * 4 + 2*j;
                const float dd0 = fminf(dist[i0],     d0);
                const float dd1 = fminf(dist[i0 + 1], d1);
                dist[i0]     = dd0;
                dist[i0 + 1] = dd1;
                if (dd0 > mv) { mv = dd0; mi = p + 2*j;     }
                if (dd1 > mv) { mv = dd1; mi = p + 2*j + 1; }
            }
        }
        far = block_argmax(mv, mi, s_wkey[(k + 1) & 1]);
    }
    __syncthreads();   // s_cent complete

    // ---- ball query: 16 warps, 64 centroids each ----
    for (int s = warp; s < NPOINT; s += NWARP) {
        const int c = s_cent[s];
        const float xs = __ldg(&base[c]);
        const float ys = __ldg(&base[NPTS + c]);
        const float zs = __ldg(&base[2 * NPTS + c]);
        const float snorm = __fmaf_rn(zs, zs,
                            __fmaf_rn(ys, ys, __fmul_rn(xs, xs)));

        int winner = NPTS;
        for (int j0 = 0; j0 < NPTS; j0 += 32) {
            const int j = j0 + lane;
            const float xj = __ldg(&base[j]);
            const float yj = __ldg(&base[NPTS + j]);
            const float zj = __ldg(&base[2 * NPTS + j]);
            const float dot   = __fmaf_rn(zs, zj,
                                __fmaf_rn(ys, yj, __fmul_rn(xs, xj)));
            const float dnorm = __fmaf_rn(zj, zj,
                                __fmaf_rn(yj, yj, __fmul_rn(xj, xj)));
            const float d = __fadd_rn(__fmaf_rn(-2.0f, dot, snorm), dnorm);
            const unsigned m = __ballot_sync(0xffffffffu, !(d > 0.25f));
            if (m) { winner = j0 + __ffs(m) - 1; break; }
        }
        if (lane == 0) out[b * NPOINT + s] = (float)winner;
    }
}

// ---------------------------------------------------------------------------
extern "C" void kernel_launch(void* const* d_in, const int* in_sizes, int n_in,
                              void* d_out, int out_size) {
    int xi = 0;
    for (int i = 0; i < n_in; i++) {
        if (in_sizes[i] == NBATCH * 3 * NPTS) { xi = i; break; }
    }
    const float* xyz = (const float*)d_in[xi];
    float* out = (float*)d_out;

    fps_kernel<<<NBATCH, NTHR>>>(xyz, out);
}

// round 12
// speedup vs baseline: 1.5045x; 1.0654x over previous
#include <cuda_runtime.h>
#include <cstdint>

#define NPTS   16384
#define NPOINT 1024
#define NBATCH 4
#define NTHR   512
#define NWARP  16
#define CHUNKS 8                 // float4 chunks per thread (4 pts each)
#define PPT    32                // points per thread

// ---- packed f32x2 helpers (per-lane bit-identical to scalar rn ops) ----
#define PACK2(out, lo, hi) \
    asm("mov.b64 %0, {%1, %2};" : "=l"(out) : "f"(lo), "f"(hi))
#define UNPACK2(lo, hi, in) \
    asm("mov.b64 {%0, %1}, %2;" : "=f"(lo), "=f"(hi) : "l"(in))
#define ADD2(out, a, b) \
    asm("add.rn.f32x2 %0, %1, %2;" : "=l"(out) : "l"(a), "l"(b))
#define MUL2(out, a, b) \
    asm("mul.rn.f32x2 %0, %1, %2;" : "=l"(out) : "l"(a), "l"(b))
#define FMA2(out, a, b, c) \
    asm("fma.rn.f32x2 %0, %1, %2, %3;" : "=l"(out) : "l"(a), "l"(b), "l"(c))

// ---------------------------------------------------------------------------
// REDUX-based block argmax for NON-NEGATIVE values (bits order == value
// order). First-occurrence tie-break via min-index among value ties.
// One barrier; s_v/s_i double-buffered by caller (parity). All lanes of all
// warps return the winning index.
// ---------------------------------------------------------------------------
__device__ __forceinline__ int block_argmax(float mv, int mi,
                                            unsigned* s_v, unsigned* s_i) {
    const int warp = threadIdx.x >> 5;
    const int lane = threadIdx.x & 31;

    const unsigned vb   = __float_as_uint(mv);
    const unsigned vmax = __reduce_max_sync(0xffffffffu, vb);
    const unsigned cand = (vb == vmax) ? (unsigned)mi : 0xFFFFFFFFu;
    const unsigned imin = __reduce_min_sync(0xffffffffu, cand);
    if (lane == 0) { s_v[warp] = vmax; s_i[warp] = imin; }
    __syncthreads();

    const unsigned tv    = (lane < NWARP) ? s_v[lane] : 0u;
    const unsigned tvmax = __reduce_max_sync(0xffffffffu, tv);
    const unsigned tcand = (lane < NWARP && tv == tvmax) ? s_i[lane]
                                                         : 0xFFFFFFFFu;
    return (int)__reduce_min_sync(0xffffffffu, tcand);
}

// ---------------------------------------------------------------------------
// Fused FPS + ball query. One CTA (512 thr) per batch. xyz layout [B,3,N].
// x,y register-resident (packed f32x2), z re-read from L1 each step.
// Per-lane FP ops bit-identical to the validated round-11 kernel.
// ---------------------------------------------------------------------------
__global__ void __launch_bounds__(NTHR, 1)
fps_kernel(const float* __restrict__ xyz, float* __restrict__ out) {
    __shared__ unsigned s_v[2][NWARP];
    __shared__ unsigned s_i[2][NWARP];
    __shared__ int s_cent[NPOINT];

    const int tid  = threadIdx.x;
    const int warp = tid >> 5;
    const int lane = tid & 31;
    const int b    = blockIdx.x;

    const float* __restrict__ base = xyz + (size_t)b * 3 * NPTS;
    const float4* __restrict__ X4 = (const float4*)base;
    const float4* __restrict__ Y4 = X4 + NPTS / 4;
    const float4* __restrict__ Z4 = Y4 + NPTS / 4;

    // ---- load x,y into packed registers; initial x-argmax on the fly ----
    // x >= 0 (uniform [0,1)), so the non-negative REDUX argmax applies.
    unsigned long long ux[2 * CHUNKS], uy[2 * CHUNKS];
    float dist[PPT];
    float mv0 = -1.0f; int mi0 = 0;
    #pragma unroll
    for (int c = 0; c < CHUNKS; c++) {
        const float4 X = __ldg(&X4[c * NTHR + tid]);
        const float4 Y = __ldg(&Y4[c * NTHR + tid]);
        PACK2(ux[2*c],     X.x, X.y);
        PACK2(ux[2*c + 1], X.z, X.w);
        PACK2(uy[2*c],     Y.x, Y.y);
        PACK2(uy[2*c + 1], Y.z, Y.w);
        const int p = (c * NTHR + tid) * 4;
        if (X.x > mv0) { mv0 = X.x; mi0 = p;     }
        if (X.y > mv0) { mv0 = X.y; mi0 = p + 1; }
        if (X.z > mv0) { mv0 = X.z; mi0 = p + 2; }
        if (X.w > mv0) { mv0 = X.w; mi0 = p + 3; }
    }
    #pragma unroll
    for (int i = 0; i < PPT; i++) dist[i] = 1e10f;

    int far = block_argmax(mv0, mi0, s_v[0], s_i[0]);

    // ---- FPS main loop ----
    for (int k = 0; k < NPOINT; k++) {
        if (tid == 0) s_cent[k] = far;

        const float cx = __ldg(&base[far]);
        const float cy = __ldg(&base[NPTS + far]);
        const float cz = __ldg(&base[2 * NPTS + far]);
        const float ncx = -cx, ncy = -cy, ncz = -cz;
        unsigned long long ncxx, ncyy;
        PACK2(ncxx, ncx, ncx);
        PACK2(ncyy, ncy, ncy);

        float mv = -1.0f; int mi = 0;
        #pragma unroll
        for (int c = 0; c < CHUNKS; c++) {
            const float4 Z = __ldg(&Z4[c * NTHR + tid]);
            const int p = (c * NTHR + tid) * 4;
            const float zs[4] = {Z.x, Z.y, Z.z, Z.w};
            #pragma unroll
            for (int j = 0; j < 2; j++) {       // pair j covers pts e=2j,2j+1
                unsigned long long dx2, dy2, t2;
                ADD2(dx2, ux[2*c + j], ncxx);   // fadd(x,-cx) == fsub(x,cx)
                ADD2(dy2, uy[2*c + j], ncyy);
                MUL2(t2, dx2, dx2);
                FMA2(t2, dy2, dy2, t2);         // dy*dy + dx*dx
                float t0, t1;
                UNPACK2(t0, t1, t2);

                const float dz0 = __fadd_rn(zs[2*j],     ncz);
                const float dz1 = __fadd_rn(zs[2*j + 1], ncz);
                const float d0  = __fmaf_rn(dz0, dz0, t0);
                const float d1  = __fmaf_rn(dz1, dz1, t1);

                const int i0 = c * 4 + 2*j;
                const float dd0 = fminf(dist[i0],     d0);
                const float dd1 = fminf(dist[i0 + 1], d1);
                dist[i0]     = dd0;
                dist[i0 + 1] = dd1;
                if (dd0 > mv) { mv = dd0; mi = p + 2*j;     }
                if (dd1 > mv) { mv = dd1; mi = p + 2*j + 1; }
            }
        }
        const int pk = (k + 1) & 1;
        far = block_argmax(mv, mi, s_v[pk], s_i[pk]);
    }
    __syncthreads();   // s_cent complete

    // ---- ball query: 16 warps, 64 centroids each ----
    for (int s = warp; s < NPOINT; s += NWARP) {
        const int c = s_cent[s];
        const float xs = __ldg(&base[c]);
        const float ys = __ldg(&base[NPTS + c]);
        const float zs = __ldg(&base[2 * NPTS + c]);
        const float snorm = __fmaf_rn(zs, zs,
                            __fmaf_rn(ys, ys, __fmul_rn(xs, xs)));

        int winner = NPTS;
        for (int j0 = 0; j0 < NPTS; j0 += 32) {
            const int j = j0 + lane;
            const float xj = __ldg(&base[j]);
            const float yj = __ldg(&base[NPTS + j]);
            const float zj = __ldg(&base[2 * NPTS + j]);
            const float dot   = __fmaf_rn(zs, zj,
                                __fmaf_rn(ys, yj, __fmul_rn(xs, xj)));
            const float dnorm = __fmaf_rn(zj, zj,
                                __fmaf_rn(yj, yj, __fmul_rn(xj, xj)));
            const float d = __fadd_rn(__fmaf_rn(-2.0f, dot, snorm), dnorm);
            const unsigned m = __ballot_sync(0xffffffffu, !(d > 0.25f));
            if (m) { winner = j0 + __ffs(m) - 1; break; }
        }
        if (lane == 0) out[b * NPOINT + s] = (float)winner;
    }
}

// ---------------------------------------------------------------------------
extern "C" void kernel_launch(void* const* d_in, const int* in_sizes, int n_in,
                              void* d_out, int out_size) {
    int xi = 0;
    for (int i = 0; i < n_in; i++) {
        if (in_sizes[i] == NBATCH * 3 * NPTS) { xi = i; break; }
    }
    const float* xyz = (const float*)d_in[xi];
    float* out = (float*)d_out;

    fps_kernel<<<NBATCH, NTHR>>>(xyz, out);
}

// round 14
// speedup vs baseline: 1.9932x; 1.3249x over previous
#include <cuda_runtime.h>
#include <cstdint>

#define NPTS   16384
#define NPOINT 1024
#define NBATCH 4
#define NTHR   512
#define NWARP  16
#define CHUNKS 8                 // float4 chunks per thread (4 pts each)
#define NPAIR  (2 * CHUNKS)      // 16 packed pairs per thread
#define PPT    32                // points per thread

// ---- packed f32x2 helpers (per-lane bit-identical to scalar rn ops) ----
#define PACK2(out, lo, hi) \
    asm("mov.b64 %0, {%1, %2};" : "=l"(out) : "f"(lo), "f"(hi))
#define UNPACK2(lo, hi, in) \
    asm("mov.b64 {%0, %1}, %2;" : "=f"(lo), "=f"(hi) : "l"(in))
#define ADD2(out, a, b) \
    asm("add.rn.f32x2 %0, %1, %2;" : "=l"(out) : "l"(a), "l"(b))
#define MUL2(out, a, b) \
    asm("mul.rn.f32x2 %0, %1, %2;" : "=l"(out) : "l"(a), "l"(b))
#define FMA2(out, a, b, c) \
    asm("fma.rn.f32x2 %0, %1, %2, %3;" : "=l"(out) : "l"(a), "l"(b), "l"(c))

// ---------------------------------------------------------------------------
// Fused FPS + ball query. One CTA (512 thr) per batch. xyz layout [B,3,N].
// Distance core fully packed f32x2 (exact order t=dx*dx; t+=dy*dy; t+=dz*dz,
// per-lane bit-identical to validated scalar chain); min/update/max scalar.
// Index resolved lazily after a value-only REDUX reduction: threads holding
// the block max scan their dists for bit-equality, min global index wins
// (exact jnp.argmax first-occurrence semantics). Float32 output.
// ---------------------------------------------------------------------------
__global__ void __launch_bounds__(NTHR, 1)
fps_kernel(const float* __restrict__ xyz, float* __restrict__ out) {
    __shared__ unsigned s_v[NWARP];
    __shared__ unsigned s_i[NWARP];
    __shared__ int s_cent[NPOINT];

    const int tid  = threadIdx.x;
    const int warp = tid >> 5;
    const int lane = tid & 31;
    const int b    = blockIdx.x;

    const float* __restrict__ base = xyz + (size_t)b * 3 * NPTS;
    const float4* __restrict__ X4 = (const float4*)base;
    const float4* __restrict__ Y4 = X4 + NPTS / 4;
    const float4* __restrict__ Z4 = Y4 + NPTS / 4;

    // ---- load x,y packed; initial x-argmax on the fly (x >= 0) ----
    unsigned long long ux[NPAIR], uy[NPAIR];
    float dist[PPT];
    float mv0 = -1.0f; int mi0 = 0;
    #pragma unroll
    for (int c = 0; c < CHUNKS; c++) {
        const float4 X = __ldg(&X4[c * NTHR + tid]);
        const float4 Y = __ldg(&Y4[c * NTHR + tid]);
        PACK2(ux[2*c],     X.x, X.y);
        PACK2(ux[2*c + 1], X.z, X.w);
        PACK2(uy[2*c],     Y.x, Y.y);
        PACK2(uy[2*c + 1], Y.z, Y.w);
        const int p = (c * NTHR + tid) * 4;
        if (X.x > mv0) { mv0 = X.x; mi0 = p;     }
        if (X.y > mv0) { mv0 = X.y; mi0 = p + 1; }
        if (X.z > mv0) { mv0 = X.z; mi0 = p + 2; }
        if (X.w > mv0) { mv0 = X.w; mi0 = p + 3; }
    }
    #pragma unroll
    for (int i = 0; i < PPT; i++) dist[i] = 1e10f;

    // ---- initial block argmax (value+index carried; runs once) ----
    int far;
    {
        const unsigned vb   = __float_as_uint(mv0);
        const unsigned wmax = __reduce_max_sync(0xffffffffu, vb);
        const unsigned cand = (vb == wmax) ? (unsigned)mi0 : 0xFFFFFFFFu;
        const unsigned imin = __reduce_min_sync(0xffffffffu, cand);
        if (lane == 0) { s_v[warp] = wmax; s_i[warp] = imin; }
        __syncthreads();
        const unsigned tv    = (lane < NWARP) ? s_v[lane] : 0u;
        const unsigned tvmax = __reduce_max_sync(0xffffffffu, tv);
        const unsigned tcand = (lane < NWARP && tv == tvmax) ? s_i[lane]
                                                             : 0xFFFFFFFFu;
        far = (int)__reduce_min_sync(0xffffffffu, tcand);
        __syncthreads();   // s_v/s_i reusable
    }

    // ---- FPS main loop ----
    for (int k = 0; k < NPOINT; k++) {
        if (tid == 0) s_cent[k] = far;

        const float cx = __ldg(&base[far]);
        const float cy = __ldg(&base[NPTS + far]);
        const float cz = __ldg(&base[2 * NPTS + far]);
        unsigned long long ncxx, ncyy, nczz;
        PACK2(ncxx, -cx, -cx);
        PACK2(ncyy, -cy, -cy);
        PACK2(nczz, -cz, -cz);

        float mvA = -1.0f, mvB = -1.0f;     // two accumulator chains
        #pragma unroll
        for (int c = 0; c < CHUNKS; c++) {
            const float4 Z = __ldg(&Z4[c * NTHR + tid]);
            unsigned long long z01, z23;
            PACK2(z01, Z.x, Z.y);
            PACK2(z23, Z.z, Z.w);
            #pragma unroll
            for (int j = 0; j < 2; j++) {
                unsigned long long dx2, dy2, dz2, t2;
                ADD2(dx2, ux[2*c + j], ncxx);   // fadd(v,-c) == fsub(v,c)
                ADD2(dy2, uy[2*c + j], ncyy);
                ADD2(dz2, (j ? z23 : z01), nczz);
                MUL2(t2, dx2, dx2);
                FMA2(t2, dy2, dy2, t2);         // dy*dy + dx*dx
                FMA2(t2, dz2, dz2, t2);         // dz*dz + (...)  exact order
                float t0, t1;
                UNPACK2(t0, t1, t2);
                const int i0 = c * 4 + 2*j;
                const float dd0 = fminf(dist[i0],     t0);
                const float dd1 = fminf(dist[i0 + 1], t1);
                dist[i0]     = dd0;
                dist[i0 + 1] = dd1;
                mvA = fmaxf(mvA, dd0);
                mvB = fmaxf(mvB, dd1);
            }
        }
        const float mv = fmaxf(mvA, mvB);

        // ---- value-only reduction (all >= 0: bit order == value order) ----
        const unsigned vb   = __float_as_uint(mv);
        const unsigned wmax = __reduce_max_sync(0xffffffffu, vb);
        if (lane == 0) s_v[warp] = wmax;
        __syncthreads();                                   // BAR 1
        const unsigned tv   = (lane < NWARP) ? s_v[lane] : 0u;
        const unsigned vmax = __reduce_max_sync(0xffffffffu, tv);

        // ---- lazy index find: only threads holding vmax scan ----
        unsigned p = 0xFFFFFFFFu;
        if (vb == vmax) {
            #pragma unroll
            for (int i = PPT - 1; i >= 0; i--) {   // descending => first occ.
                if (__float_as_uint(dist[i]) == vmax)
                    p = (unsigned)(((i >> 2) * NTHR + tid) * 4 + (i & 3));
            }
        }
        const unsigned pw = __reduce_min_sync(0xffffffffu, p);
        if (lane == 0) s_i[warp] = pw;
        __syncthreads();                                   // BAR 2
        const unsigned ti = (lane < NWARP) ? s_i[lane] : 0xFFFFFFFFu;
        far = (int)__reduce_min_sync(0xffffffffu, ti);
    }
    __syncthreads();   // s_cent complete

    // ---- ball query: 16 warps, 64 centroids each ----
    for (int s = warp; s < NPOINT; s += NWARP) {
        const int c = s_cent[s];
        const float xs = __ldg(&base[c]);
        const float ys = __ldg(&base[NPTS + c]);
        const float zs = __ldg(&base[2 * NPTS + c]);
        const float snorm = __fmaf_rn(zs, zs,
                            __fmaf_rn(ys, ys, __fmul_rn(xs, xs)));

        int winner = NPTS;
        for (int j0 = 0; j0 < NPTS; j0 += 32) {
            const int j = j0 + lane;
            const float xj = __ldg(&base[j]);
            const float yj = __ldg(&base[NPTS + j]);
            const float zj = __ldg(&base[2 * NPTS + j]);
            const float dot   = __fmaf_rn(zs, zj,
                                __fmaf_rn(ys, yj, __fmul_rn(xs, xj)));
            const float dnorm = __fmaf_rn(zj, zj,
                                __fmaf_rn(yj, yj, __fmul_rn(xj, xj)));
            const float d = __fadd_rn(__fmaf_rn(-2.0f, dot, snorm), dnorm);
            const unsigned m = __ballot_sync(0xffffffffu, !(d > 0.25f));
            if (m) { winner = j0 + __ffs(m) - 1; break; }
        }
        if (lane == 0) out[b * NPOINT + s] = (float)winner;
    }
}

// ---------------------------------------------------------------------------
extern "C" void kernel_launch(void* const* d_in, const int* in_sizes, int n_in,
                              void* d_out, int out_size) {
    int xi = 0;
    for (int i = 0; i < n_in; i++) {
        if (in_sizes[i] == NBATCH * 3 * NPTS) { xi = i; break; }
    }
    const float* xyz = (const float*)d_in[xi];
    float* out = (float*)d_out;

    fps_kernel<<<NBATCH, NTHR>>>(xyz, out);
}